// round 11
// baseline (speedup 1.0000x reference)
#include <cuda_runtime.h>
#include <math.h>

// Problem constants
#define BATCH 4096
#define DIM   64

// Tiling: 64-thread CTA = 2 cooperating warps. CTA owns R=4 batch rows.
// Lane l owns output comps i=l and i=l+32; warp w owns j-half [32w, 32w+32).
// 1024 CTAs -> 2048 warps (~13.8/SM), 16 FMA chains/warp, ~140 regs.
#define R        4
#define THREADS  64
#define NBLOCKS  (BATCH / R)      // 1024

#define MAX_IT   50
#define DTOL     2e-3f
#define N_FINAL  3                // accurate-tanh polish iterations

#define WPITCH 68   // W staging pitch (conflict-free strided LDS.128)

typedef unsigned long long u64;

__device__ __forceinline__ u64 pk(float lo, float hi) {
    u64 r; asm("mov.b64 %0, {%1, %2};" : "=l"(r) : "f"(lo), "f"(hi)); return r;
}
__device__ __forceinline__ void upk(float& lo, float& hi, u64 v) {
    asm("mov.b64 {%0, %1}, %2;" : "=f"(lo), "=f"(hi) : "l"(v));
}
__device__ __forceinline__ void fma2(u64& d, u64 a, u64 b) {
    asm("fma.rn.f32x2 %0, %1, %2, %0;" : "+l"(d) : "l"(a), "l"(b));
}
__device__ __forceinline__ u64 add2(u64 a, u64 b) {
    u64 r; asm("add.rn.f32x2 %0, %1, %2;" : "=l"(r) : "l"(a), "l"(b)); return r;
}

// Fast hw tanh: 1 MUFU, max err ~6e-4 (fine while iteration still contracts).
__device__ __forceinline__ float tanh_fast(float a) {
    float t; asm("tanh.approx.f32 %0, %1;" : "=f"(t) : "f"(a)); return t;
}
// Accurate tanh (~1e-6): EX2 + Newton-refined reciprocal, fast-math-proof.
__device__ __forceinline__ float tanh_acc(float a) {
    float aa = fabsf(a);
    float e;
    asm("ex2.approx.ftz.f32 %0, %1;" : "=f"(e) : "f"(aa * -2.8853900817779268f));
    float d = 1.0f + e;
    float r = fmaf(-0.49043f, d, 1.4571f);
    r = r * (2.0f - d * r);
    r = r * (2.0f - d * r);
    return copysignf((1.0f - e) * r, a);
}

__global__ void __launch_bounds__(THREADS)
tanh_fixed_point_kernel(const float* __restrict__ x,
                        const float* __restrict__ W,
                        float* __restrict__ out)
{
    __shared__ __align__(16) float  Wsh[DIM * WPITCH];        // one-time stage
    __shared__ __align__(16) float  zsh[R][DIM];              // current z (redundant identical writes)
    __shared__ __align__(16) float2 psh[2][2][R][32];         // ping-pong partials [pp][warp][r][lane]

    const int tid  = threadIdx.x;
    const int lane = tid & 31;
    const int warp = tid >> 5;

    // Stage W into shared (coalesced float4)
    for (int v = tid; v < (DIM * DIM) / 4; v += THREADS) {
        int i = v >> 4;          // row
        int k = v & 15;          // quad within row
        float4 f = reinterpret_cast<const float4*>(W)[v];
        *reinterpret_cast<float4*>(&Wsh[i * WPITCH + 4 * k]) = f;
    }
    __syncthreads();

    // W regs: my j-half of rows i=lane (A) and i=lane+32 (B), packed j-pairs.
    const int jbase = warp * 32;
    u64 wA[16], wB[16];
    {
        const ulonglong2* rowA = reinterpret_cast<const ulonglong2*>(&Wsh[lane * WPITCH + jbase]);
        const ulonglong2* rowB = reinterpret_cast<const ulonglong2*>(&Wsh[(lane + 32) * WPITCH + jbase]);
        #pragma unroll
        for (int q = 0; q < 8; q++) {
            ulonglong2 va = rowA[q];
            ulonglong2 vb = rowB[q];
            wA[2 * q] = va.x; wA[2 * q + 1] = va.y;
            wB[2 * q] = vb.x; wB[2 * q + 1] = vb.y;
        }
    }

    const int row0 = blockIdx.x * R;

    float xrA[R], xrB[R], zA[R], zB[R];
    #pragma unroll
    for (int r = 0; r < R; r++) {
        xrA[r] = x[(row0 + r) * DIM + lane];
        xrB[r] = x[(row0 + r) * DIM + lane + 32];
        zA[r]  = tanh_acc(xrA[r]);
        zB[r]  = tanh_acc(xrB[r]);
        zsh[r][lane]      = zA[r];   // both warps write identical values: benign
        zsh[r][lane + 32] = zB[r];
    }
    __syncwarp();

    int pp = 0;

    // One Picard iteration (j-split). Returns per-thread convergence flag.
    // x is NOT in the partials; it is added exactly once at the combine.
    auto do_iter = [&](bool approx) -> bool {
        // 16 independent packed chains, depth 8
        u64 a0A[R], a1A[R], a0B[R], a1B[R];
        #pragma unroll
        for (int r = 0; r < R; r++) {
            a0A[r] = pk(0.0f, 0.0f);  a1A[r] = pk(0.0f, 0.0f);
            a0B[r] = pk(0.0f, 0.0f);  a1B[r] = pk(0.0f, 0.0f);
        }
        #pragma unroll
        for (int q2 = 0; q2 < 8; q2++) {
            #pragma unroll
            for (int r = 0; r < R; r++) {
                ulonglong2 zp =
                    (reinterpret_cast<const ulonglong2*>(zsh[r]) + 8 * warp)[q2];
                fma2(a0A[r], wA[2 * q2],     zp.x);
                fma2(a1A[r], wA[2 * q2 + 1], zp.y);
                fma2(a0B[r], wB[2 * q2],     zp.x);
                fma2(a1B[r], wB[2 * q2 + 1], zp.y);
            }
        }
        // Horizontal combine -> my-half partials
        float pA[R], pB[R];
        #pragma unroll
        for (int r = 0; r < R; r++) {
            float lo, hi;
            u64 sA = add2(a0A[r], a1A[r]);
            upk(lo, hi, sA); pA[r] = lo + hi;
            u64 sB = add2(a0B[r], a1B[r]);
            upk(lo, hi, sB); pB[r] = lo + hi;
            psh[pp][warp][r][lane] = make_float2(pA[r], pB[r]);
        }
        __syncthreads();    // partials visible cross-warp

        bool conv = true;
        #pragma unroll
        for (int r = 0; r < R; r++) {
            float2 q = psh[pp][warp ^ 1][r][lane];
            // x added exactly once here; (p_mine + p_other) commutes -> both
            // warps produce bitwise-identical zl, z, and conv flags.
            float zlA = (pA[r] + q.x) + xrA[r];
            float zlB = (pB[r] + q.y) + xrB[r];
            float nA = approx ? tanh_fast(zlA) : tanh_acc(zlA);
            float nB = approx ? tanh_fast(zlB) : tanh_acc(zlB);
            conv = conv && (fabsf(nA - zA[r]) < DTOL) && (fabsf(nB - zB[r]) < DTOL);
            zA[r] = nA; zB[r] = nB;
            zsh[r][lane]      = nA;      // redundant identical writes from both warps
            zsh[r][lane + 32] = nB;
        }
        pp ^= 1;
        __syncwarp();       // own-warp z stores visible for next iter's loads
        return conv;
    };

    // Phase 1: cheap-tanh contraction with convergence vote
    for (int it = 0; it < MAX_IT; it++) {
        bool conv = do_iter(true);
        if (__all_sync(0xffffffffu, conv)) break;   // identical vote in both warps
    }
    // Phase 2: fixed accurate-tanh polish
    #pragma unroll
    for (int f = 0; f < N_FINAL; f++) (void)do_iter(false);

    // Each warp writes 2 rows (values identical across warps)
    #pragma unroll
    for (int r = 0; r < 2; r++) {
        int rr = warp * 2 + r;
        out[(row0 + rr) * DIM + lane]      = zA[rr];
        out[(row0 + rr) * DIM + lane + 32] = zB[rr];
    }
}

extern "C" void kernel_launch(void* const* d_in, const int* in_sizes, int n_in,
                              void* d_out, int out_size)
{
    const float* x = (const float*)d_in[0];   // [4096, 64]
    const float* W = (const float*)d_in[1];   // [64, 64]
    float* out = (float*)d_out;               // [4096, 64]
    (void)in_sizes; (void)n_in; (void)out_size;

    tanh_fixed_point_kernel<<<NBLOCKS, THREADS>>>(x, W, out);
}

// round 12
// speedup vs baseline: 1.1180x; 1.1180x over previous
#include <cuda_runtime.h>
#include <math.h>

// Problem constants
#define BATCH 4096
#define DIM   64

// Tiling: 128-thread CTA = 4 warps = 2 row-groups x 2 j-halves.
// warp w: g = w>>1 (row group, 4 rows), h = w&1 (j-half [32h, 32h+32)).
// Lane l owns comps i=l (A) and i=l+32 (B). 512 CTAs -> 2048 warps,
// spread over ALL 4 SMSPs (wid%4 covers 0..3). ~130 regs.
#define R        4                 // rows per row-group
#define THREADS  128
#define ROWS_PER_BLOCK 8
#define NBLOCKS  (BATCH / ROWS_PER_BLOCK)   // 512

#define MAX_IT   50
#define DTOL     2e-3f
#define N_FINAL  1                 // accurate-tanh polish iterations

#define WPITCH 68   // W staging pitch (conflict-free strided LDS.128)

typedef unsigned long long u64;

__device__ __forceinline__ u64 pk0() {
    u64 r; asm("mov.b64 %0, {%1, %2};" : "=l"(r) : "f"(0.0f), "f"(0.0f)); return r;
}
__device__ __forceinline__ void upk(float& lo, float& hi, u64 v) {
    asm("mov.b64 {%0, %1}, %2;" : "=f"(lo), "=f"(hi) : "l"(v));
}
__device__ __forceinline__ void fma2(u64& d, u64 a, u64 b) {
    asm("fma.rn.f32x2 %0, %1, %2, %0;" : "+l"(d) : "l"(a), "l"(b));
}
__device__ __forceinline__ u64 add2(u64 a, u64 b) {
    u64 r; asm("add.rn.f32x2 %0, %1, %2;" : "=l"(r) : "l"(a), "l"(b)); return r;
}

// Fast hw tanh: 1 MUFU (err small; residual removed by polish + contraction).
__device__ __forceinline__ float tanh_fast(float a) {
    float t; asm("tanh.approx.f32 %0, %1;" : "=f"(t) : "f"(a)); return t;
}
// Accurate tanh (~1e-6): EX2 + Newton-refined reciprocal, fast-math-proof.
__device__ __forceinline__ float tanh_acc(float a) {
    float aa = fabsf(a);
    float e;
    asm("ex2.approx.ftz.f32 %0, %1;" : "=f"(e) : "f"(aa * -2.8853900817779268f));
    float d = 1.0f + e;
    float r = fmaf(-0.49043f, d, 1.4571f);
    r = r * (2.0f - d * r);
    r = r * (2.0f - d * r);
    return copysignf((1.0f - e) * r, a);
}

__global__ void __launch_bounds__(THREADS)
tanh_fixed_point_kernel(const float* __restrict__ x,
                        const float* __restrict__ W,
                        float* __restrict__ out)
{
    __shared__ __align__(16) float  Wsh[DIM * WPITCH];     // one-time stage
    __shared__ __align__(16) float  zsh[2][R][DIM];        // z per row-group (redundant writes)
    __shared__ __align__(16) float2 psh[2][4][R][32];      // ping-pong partials [pp][warp][r][lane]

    const int tid  = threadIdx.x;
    const int lane = tid & 31;
    const int warp = tid >> 5;
    const int g    = warp >> 1;    // row group
    const int h    = warp & 1;     // j-half

    // Stage W into shared (coalesced float4 loads)
    for (int v = tid; v < (DIM * DIM) / 4; v += THREADS) {
        int i = v >> 4;
        int k = v & 15;
        float4 f = reinterpret_cast<const float4*>(W)[v];
        *reinterpret_cast<float4*>(&Wsh[i * WPITCH + 4 * k]) = f;
    }
    __syncthreads();

    // W regs: my j-half of rows i=lane (A) and i=lane+32 (B), packed j-pairs.
    const int jbase = h * 32;
    u64 wA[16], wB[16];
    {
        const ulonglong2* rowA = reinterpret_cast<const ulonglong2*>(&Wsh[lane * WPITCH + jbase]);
        const ulonglong2* rowB = reinterpret_cast<const ulonglong2*>(&Wsh[(lane + 32) * WPITCH + jbase]);
        #pragma unroll
        for (int q = 0; q < 8; q++) {
            ulonglong2 va = rowA[q];
            ulonglong2 vb = rowB[q];
            wA[2 * q] = va.x; wA[2 * q + 1] = va.y;
            wB[2 * q] = vb.x; wB[2 * q + 1] = vb.y;
        }
    }

    const int row0 = blockIdx.x * ROWS_PER_BLOCK + g * R;

    float xrA[R], xrB[R], zA[R], zB[R];
    #pragma unroll
    for (int r = 0; r < R; r++) {
        xrA[r] = x[(row0 + r) * DIM + lane];
        xrB[r] = x[(row0 + r) * DIM + lane + 32];
        zA[r]  = tanh_acc(xrA[r]);
        zB[r]  = tanh_acc(xrB[r]);
        zsh[g][r][lane]      = zA[r];   // both j-halves write identical values
        zsh[g][r][lane + 32] = zB[r];
    }
    __syncthreads();

    int pp = 0;
    bool convPrev = false;   // delayed vote: conv of iteration k voted inside k+1

    // One Picard iteration (j-split). x added exactly once at the combine.
    auto do_iter = [&](bool approx, bool vote) -> bool {
        // 16 independent packed chains, depth 8. Reads own-warp zsh stores
        // (redundant identical copies -> no cross-warp ordering needed here).
        u64 a0A[R], a1A[R], a0B[R], a1B[R];
        #pragma unroll
        for (int r = 0; r < R; r++) {
            a0A[r] = pk0();  a1A[r] = pk0();
            a0B[r] = pk0();  a1B[r] = pk0();
        }
        #pragma unroll
        for (int q2 = 0; q2 < 8; q2++) {
            #pragma unroll
            for (int r = 0; r < R; r++) {
                ulonglong2 zp =
                    (reinterpret_cast<const ulonglong2*>(zsh[g][r]) + 8 * h)[q2];
                fma2(a0A[r], wA[2 * q2],     zp.x);
                fma2(a1A[r], wA[2 * q2 + 1], zp.y);
                fma2(a0B[r], wB[2 * q2],     zp.x);
                fma2(a1B[r], wB[2 * q2 + 1], zp.y);
            }
        }
        float pA[R], pB[R];
        #pragma unroll
        for (int r = 0; r < R; r++) {
            float lo, hi;
            u64 sA = add2(a0A[r], a1A[r]);
            upk(lo, hi, sA); pA[r] = lo + hi;
            u64 sB = add2(a0B[r], a1B[r]);
            upk(lo, hi, sB); pB[r] = lo + hi;
            psh[pp][warp][r][lane] = make_float2(pA[r], pB[r]);
        }
        // Single block barrier: publishes partials AND votes previous conv.
        int allc = __syncthreads_and((vote && convPrev) ? 1 : 0);
        if (vote && allc) return true;     // uniform across block

        bool conv = true;
        #pragma unroll
        for (int r = 0; r < R; r++) {
            float2 q = psh[pp][warp ^ 1][r][lane];
            // (p_mine + p_partner) commutes -> both halves bitwise identical.
            float zlA = (pA[r] + q.x) + xrA[r];
            float zlB = (pB[r] + q.y) + xrB[r];
            float nA = approx ? tanh_fast(zlA) : tanh_acc(zlA);
            float nB = approx ? tanh_fast(zlB) : tanh_acc(zlB);
            conv = conv && (fabsf(nA - zA[r]) < DTOL) && (fabsf(nB - zB[r]) < DTOL);
            zA[r] = nA; zB[r] = nB;
            zsh[g][r][lane]      = nA;    // redundant identical writes
            zsh[g][r][lane + 32] = nB;
        }
        convPrev = conv;
        pp ^= 1;
        return false;
    };

    // Phase 1: fast-tanh contraction with delayed block-wide vote
    for (int it = 0; it < MAX_IT; it++) {
        if (do_iter(true, true)) break;
    }
    // Phase 2: accurate-tanh polish (fixed count, no vote)
    #pragma unroll
    for (int f = 0; f < N_FINAL; f++) (void)do_iter(false, false);

    // Each warp writes 2 of its group's 4 rows (values identical across halves)
    #pragma unroll
    for (int rr = 0; rr < 2; rr++) {
        int r = h * 2 + rr;
        out[(row0 + r) * DIM + lane]      = zA[r];
        out[(row0 + r) * DIM + lane + 32] = zB[r];
    }
}

extern "C" void kernel_launch(void* const* d_in, const int* in_sizes, int n_in,
                              void* d_out, int out_size)
{
    const float* x = (const float*)d_in[0];   // [4096, 64]
    const float* W = (const float*)d_in[1];   // [64, 64]
    float* out = (float*)d_out;               // [4096, 64]
    (void)in_sizes; (void)n_in; (void)out_size;

    tanh_fixed_point_kernel<<<NBLOCKS, THREADS>>>(x, W, out);
}